// round 14
// baseline (speedup 1.0000x reference)
#include <cuda_runtime.h>
#include <cuda_bf16.h>
#include <cuda_fp16.h>
#include <stdint.h>

#define MAX_USERS 100000
#define EMBED 128
#define TILE_M 128           // rows per GEMM CTA

// ---------------------------------------------------------------------------
// Scratch in __device__ globals (no allocation allowed anywhere)
// ---------------------------------------------------------------------------
__device__ uint16_t g_xtb[(size_t)MAX_USERS * EMBED]; // x @ W result, bf16
__device__ int      g_row_ptr[MAX_USERS + 1];
__device__ uint16_t g_wt[2][EMBED * EMBED];           // [layer] W^T fp16, [n][k]

// ---------------------------------------------------------------------------
// SMEM: x (128x256B) | w (128x256B) = 64KB.
// Swizzle: addr = row*256 + (kb ^ ((row&7)<<4)) (verified R5/R8-R13).
// ---------------------------------------------------------------------------
#define SM_XH 0
#define SM_WH 32768
#define SM_TOTAL 65536

__device__ __forceinline__ uint32_t smem_u32(const void* p) {
    uint32_t a;
    asm("{ .reg .u64 t; cvta.to.shared.u64 t, %1; cvt.u32.u64 %0, t; }" : "=r"(a) : "l"(p));
    return a;
}

#define LDSM_X4(f0, f1, f2, f3, addr) \
    asm volatile("ldmatrix.sync.aligned.m8n8.x4.shared.b16 {%0,%1,%2,%3}, [%4];" \
        : "=r"(f0), "=r"(f1), "=r"(f2), "=r"(f3) : "r"(addr))

#define MMA_F16(c0, c1, c2, c3, a0, a1, a2, a3, b0, b1) \
    asm volatile("mma.sync.aligned.m16n8k16.row.col.f32.f16.f16.f32 " \
        "{%0,%1,%2,%3}, {%4,%5,%6,%7}, {%8,%9}, {%0,%1,%2,%3};" \
        : "+f"(c0), "+f"(c1), "+f"(c2), "+f"(c3) \
        : "r"(a0), "r"(a1), "r"(a2), "r"(a3), "r"(b0), "r"(b1))

__device__ __forceinline__ uint32_t h2_bits(float a, float b) {
    __half2 h = __floats2half2_rn(a, b);
    return *(uint32_t*)&h;
}
__device__ __forceinline__ uint32_t bf2_bits(float a, float b) {
    __nv_bfloat16 x = __float2bfloat16(a), y = __float2bfloat16(b);
    return (uint32_t)*(uint16_t*)&x | ((uint32_t)*(uint16_t*)&y << 16);
}

// ---------------------------------------------------------------------------
// Fused prep: blocks [0,128) convert W -> W^T fp16; blocks [128, ...) build
// CSR row_ptr from sorted s_rows. One launch instead of two.
// ---------------------------------------------------------------------------
__global__ void prep_kernel(const float* __restrict__ W0, const float* __restrict__ W1,
                            const int* __restrict__ rows, int E, int M) {
    int b = blockIdx.x;
    if (b < 128) {
        int layer = b >> 6;
        int idx = (b & 63) * 256 + threadIdx.x;   // 0..16383
        const float* W = layer ? W1 : W0;
        int k = idx >> 7, n = idx & 127;
        __half h = __float2half_rn(W[idx]);
        g_wt[layer][n * EMBED + k] = *(uint16_t*)&h;
    } else {
        int e = (b - 128) * 256 + threadIdx.x;
        if (e >= E) return;
        int r = rows[e];
        if (e == 0) { for (int i = 0; i <= r; i++) g_row_ptr[i] = 0; }
        else { int rp = rows[e - 1]; for (int i = rp + 1; i <= r; i++) g_row_ptr[i] = e; }
        if (e == E - 1) { for (int i = r + 1; i <= M; i++) g_row_ptr[i] = E; }
    }
}

// ---------------------------------------------------------------------------
// fp16 1-product HMMA GEMM: Xtb(bf16) = A[M,128] @ W[128,128]  (R13, verified)
// CTA: 256 threads / 8 warps; TILE_M=128; warp w: rows w*16..+15, all 128 cols.
// ---------------------------------------------------------------------------
__global__ __launch_bounds__(256, 2) void gemm_f16_kernel(const float* __restrict__ A,
                                                          int layer,
                                                          uint16_t* __restrict__ Xtb,
                                                          int M) {
    extern __shared__ char smem[];
    const uint32_t sb = smem_u32(smem);
    const int tid = threadIdx.x;
    const int wid = tid >> 5;
    const int lid = tid & 31;
    const int row0 = blockIdx.x * TILE_M;

    // ---- Stage W^T fp16 (swizzled): thread t -> n = t>>1, 128B half h = t&1
    {
        const uint4* gh = (const uint4*)g_wt[layer];
        int n = tid >> 1, h = tid & 1;
        uint32_t nsw = (uint32_t)((n & 7) << 4);
        uint32_t rbase = (uint32_t)(n * 256);
#pragma unroll
        for (int c = 0; c < 8; c++) {
            uint32_t kb = (uint32_t)(h * 128 + c * 16);
            *(uint4*)(smem + SM_WH + rbase + (kb ^ nsw)) = gh[n * 16 + h * 8 + c];
        }
    }

    // ---- Stage A rows -> fp16 (swizzled): thread t -> row t&127, half t>>7
    {
        int r = tid & 127, h = tid >> 7;
        int grow = row0 + r;
        if (grow >= M) grow = M - 1;
        const float4* src = (const float4*)(A + (size_t)grow * EMBED + h * 64);
        uint32_t rsw = (uint32_t)((r & 7) << 4);
        uint32_t rbase = (uint32_t)(r * 256);
#pragma unroll
        for (int c = 0; c < 8; c++) {            // 8 x 16B chunks (8 fp16 each)
            float4 f0 = src[c * 2];
            float4 f1 = src[c * 2 + 1];
            uint4 v = make_uint4(h2_bits(f0.x, f0.y), h2_bits(f0.z, f0.w),
                                 h2_bits(f1.x, f1.y), h2_bits(f1.z, f1.w));
            uint32_t kb = (uint32_t)(h * 128 + c * 16);
            *(uint4*)(smem + SM_XH + rbase + (kb ^ rsw)) = v;
        }
    }
    __syncthreads();

    // ---- Fragment addressing (verified mapping); warp owns rows wid*16..+15
    const uint32_t lsw = (uint32_t)((lid & 7) << 4);

    const int a_m = (((lid >> 3) & 1) << 3) + (lid & 7);
    const uint32_t a_kb0 = (uint32_t)((((lid >> 4) & 1) << 3) * 2);
    const uint32_t a_rbase = (uint32_t)((wid * 16 + a_m) * 256);

    const int b_nl = (((lid >> 4) & 1) << 3) + (lid & 7);
    const uint32_t b_kb0 = (uint32_t)((((lid >> 3) & 1) << 3) * 2);
    const uint32_t b_rbase0 = (uint32_t)(b_nl * 256);

    float acc[16][4];
#pragma unroll
    for (int nb = 0; nb < 16; nb++)
#pragma unroll
        for (int i = 0; i < 4; i++) acc[nb][i] = 0.f;

#pragma unroll
    for (int ks = 0; ks < 8; ks++) {
        const uint32_t akb = (a_kb0 + (uint32_t)(ks * 32)) ^ lsw;
        const uint32_t bkb = (b_kb0 + (uint32_t)(ks * 32)) ^ lsw;
        uint32_t a0, a1, a2, a3;
        LDSM_X4(a0, a1, a2, a3, sb + SM_XH + a_rbase + akb);
#pragma unroll
        for (int p = 0; p < 8; p++) {
            const uint32_t brow = b_rbase0 + (uint32_t)(p * 16 * 256);
            uint32_t b0, b1, b2, b3;
            LDSM_X4(b0, b1, b2, b3, sb + SM_WH + brow + bkb);
            MMA_F16(acc[2 * p][0], acc[2 * p][1], acc[2 * p][2], acc[2 * p][3],
                    a0, a1, a2, a3, b0, b1);
            MMA_F16(acc[2 * p + 1][0], acc[2 * p + 1][1], acc[2 * p + 1][2], acc[2 * p + 1][3],
                    a0, a1, a2, a3, b2, b3);
        }
    }

    // ---- Epilogue: write bf16 xt
    const int g = lid >> 2;
    const int q = lid & 3;
    const int m0 = row0 + wid * 16 + g;
    const int m1 = m0 + 8;
#pragma unroll
    for (int nb = 0; nb < 16; nb++) {
        int col = nb * 8 + q * 2;
        if (m0 < M) *(uint32_t*)(Xtb + (size_t)m0 * EMBED + col) = bf2_bits(acc[nb][0], acc[nb][1]);
        if (m1 < M) *(uint32_t*)(Xtb + (size_t)m1 * EMBED + col) = bf2_bits(acc[nb][2], acc[nb][3]);
    }
}

// ---------------------------------------------------------------------------
// SpMM + residual, bf16 gather, row-constant value, 2-way unrolled with DUAL
// accumulators: two independent gathers in flight per iteration, add chains
// on disjoint registers -> 2x exposed memory parallelism per warp.
//   out[r] = x[r] + v_r * sum_e bf16(xt)[cols[e]]
// ---------------------------------------------------------------------------
__global__ __launch_bounds__(256) void spmm_kernel(const float* __restrict__ x,
                                                   const int* __restrict__ cols,
                                                   const float* __restrict__ vals,
                                                   float* __restrict__ out,
                                                   float* __restrict__ out0,
                                                   int M) {
    int warp = (blockIdx.x * blockDim.x + threadIdx.x) >> 5;
    int lane = threadIdx.x & 31;
    if (warp >= M) return;
    int r = warp;
    int s = g_row_ptr[r];
    int e = g_row_ptr[r + 1];
    float vrow = (s < e) ? __ldg(vals + s) : 0.f;   // constant within the row

    float4 acc0 = make_float4(0.f, 0.f, 0.f, 0.f);
    float4 acc1 = make_float4(0.f, 0.f, 0.f, 0.f);

    for (int base = s; base < e; base += 32) {
        int idx = base + lane;
        int c = 0;
        if (idx < e) c = __ldg(cols + idx);
        int cnt = min(32, e - base);
        int j = 0;
        for (; j + 2 <= cnt; j += 2) {
            int cj0 = __shfl_sync(0xffffffffu, c, j);
            int cj1 = __shfl_sync(0xffffffffu, c, j + 1);
            uint2 r0 = ((const uint2*)(g_xtb + (size_t)cj0 * EMBED))[lane];
            uint2 r1 = ((const uint2*)(g_xtb + (size_t)cj1 * EMBED))[lane];
            acc0.x += __uint_as_float(r0.x << 16);
            acc0.y += __uint_as_float(r0.x & 0xffff0000u);
            acc0.z += __uint_as_float(r0.y << 16);
            acc0.w += __uint_as_float(r0.y & 0xffff0000u);
            acc1.x += __uint_as_float(r1.x << 16);
            acc1.y += __uint_as_float(r1.x & 0xffff0000u);
            acc1.z += __uint_as_float(r1.y << 16);
            acc1.w += __uint_as_float(r1.y & 0xffff0000u);
        }
        if (j < cnt) {
            int cj = __shfl_sync(0xffffffffu, c, j);
            uint2 r0 = ((const uint2*)(g_xtb + (size_t)cj * EMBED))[lane];
            acc0.x += __uint_as_float(r0.x << 16);
            acc0.y += __uint_as_float(r0.x & 0xffff0000u);
            acc0.z += __uint_as_float(r0.y << 16);
            acc0.w += __uint_as_float(r0.y & 0xffff0000u);
        }
    }

    float4 xv = ((const float4*)(x + (size_t)r * EMBED))[lane];
    if (out0) ((float4*)(out0 + (size_t)r * EMBED))[lane] = xv;
    float4 o;
    o.x = fmaf(vrow, acc0.x + acc1.x, xv.x);
    o.y = fmaf(vrow, acc0.y + acc1.y, xv.y);
    o.z = fmaf(vrow, acc0.z + acc1.z, xv.z);
    o.w = fmaf(vrow, acc0.w + acc1.w, xv.w);
    ((float4*)(out + (size_t)r * EMBED))[lane] = o;
}

// ---------------------------------------------------------------------------
// kernel_launch
// ---------------------------------------------------------------------------
extern "C" void kernel_launch(void* const* d_in, const int* in_sizes, int n_in,
                              void* d_out, int out_size) {
    const float* ue   = (const float*)d_in[0];
    const int*   rows = (const int*)  d_in[1];
    const int*   cols = (const int*)  d_in[2];
    const float* vals = (const float*)d_in[3];
    const float* W0   = (const float*)d_in[4];
    const float* W1   = (const float*)d_in[5];
    float* out = (float*)d_out;

    const int M = in_sizes[0] / EMBED;
    const int E = in_sizes[1];
    const size_t layer_elems = (size_t)M * EMBED;

    uint16_t* xtb_ptr;
    cudaGetSymbolAddress((void**)&xtb_ptr, g_xtb);

    cudaFuncSetAttribute(gemm_f16_kernel, cudaFuncAttributeMaxDynamicSharedMemorySize, SM_TOTAL);

    // Fused W-prep + CSR row_ptr build (one launch)
    prep_kernel<<<128 + (E + 255) / 256, 256>>>(W0, W1, rows, E, M);

    const int gemm_blocks = (M + TILE_M - 1) / TILE_M;
    const int spmm_blocks = (M * 32 + 255) / 256;

    // Layer 1 (SpMM also emits out[0] = user_embeds)
    gemm_f16_kernel<<<gemm_blocks, 256, SM_TOTAL>>>(ue, 0, xtb_ptr, M);
    spmm_kernel<<<spmm_blocks, 256>>>(ue, cols, vals, out + layer_elems, out, M);

    // Layer 2
    gemm_f16_kernel<<<gemm_blocks, 256, SM_TOTAL>>>(out + layer_elems, 1, xtb_ptr, M);
    spmm_kernel<<<spmm_blocks, 256>>>(out + layer_elems, cols, vals,
                                      out + 2 * layer_elems, nullptr, M);
}

// round 15
// speedup vs baseline: 1.1484x; 1.1484x over previous
#include <cuda_runtime.h>
#include <cuda_bf16.h>
#include <cuda_fp16.h>
#include <stdint.h>

#define MAX_USERS 100000
#define EMBED 128
#define TILE_M 128           // rows per GEMM CTA

// ---------------------------------------------------------------------------
// Scratch in __device__ globals (no allocation allowed anywhere)
// ---------------------------------------------------------------------------
__device__ uint16_t g_xtb[(size_t)MAX_USERS * EMBED]; // x @ W result, bf16
__device__ int      g_row_ptr[MAX_USERS + 1];
__device__ uint16_t g_wt[2][EMBED * EMBED];           // [layer] W^T fp16, [n][k]

// ---------------------------------------------------------------------------
// SMEM: x (128x256B) | w (128x256B) = 64KB.
// Swizzle: addr = row*256 + (kb ^ ((row&7)<<4)) (verified R5/R8-R14).
// ---------------------------------------------------------------------------
#define SM_XH 0
#define SM_WH 32768
#define SM_TOTAL 65536

__device__ __forceinline__ uint32_t smem_u32(const void* p) {
    uint32_t a;
    asm("{ .reg .u64 t; cvta.to.shared.u64 t, %1; cvt.u32.u64 %0, t; }" : "=r"(a) : "l"(p));
    return a;
}

#define LDSM_X4(f0, f1, f2, f3, addr) \
    asm volatile("ldmatrix.sync.aligned.m8n8.x4.shared.b16 {%0,%1,%2,%3}, [%4];" \
        : "=r"(f0), "=r"(f1), "=r"(f2), "=r"(f3) : "r"(addr))

#define MMA_F16(c0, c1, c2, c3, a0, a1, a2, a3, b0, b1) \
    asm volatile("mma.sync.aligned.m16n8k16.row.col.f32.f16.f16.f32 " \
        "{%0,%1,%2,%3}, {%4,%5,%6,%7}, {%8,%9}, {%0,%1,%2,%3};" \
        : "+f"(c0), "+f"(c1), "+f"(c2), "+f"(c3) \
        : "r"(a0), "r"(a1), "r"(a2), "r"(a3), "r"(b0), "r"(b1))

__device__ __forceinline__ uint32_t h2_bits(float a, float b) {
    __half2 h = __floats2half2_rn(a, b);
    return *(uint32_t*)&h;
}
__device__ __forceinline__ uint32_t bf2_bits(float a, float b) {
    __nv_bfloat16 x = __float2bfloat16(a), y = __float2bfloat16(b);
    return (uint32_t)*(uint16_t*)&x | ((uint32_t)*(uint16_t*)&y << 16);
}

// ---------------------------------------------------------------------------
// Fused prep: blocks [0,128) convert W -> W^T fp16; blocks [128, ...) build
// CSR row_ptr from sorted s_rows.
// ---------------------------------------------------------------------------
__global__ void prep_kernel(const float* __restrict__ W0, const float* __restrict__ W1,
                            const int* __restrict__ rows, int E, int M) {
    int b = blockIdx.x;
    if (b < 128) {
        int layer = b >> 6;
        int idx = (b & 63) * 256 + threadIdx.x;   // 0..16383
        const float* W = layer ? W1 : W0;
        int k = idx >> 7, n = idx & 127;
        __half h = __float2half_rn(W[idx]);
        g_wt[layer][n * EMBED + k] = *(uint16_t*)&h;
    } else {
        int e = (b - 128) * 256 + threadIdx.x;
        if (e >= E) return;
        int r = rows[e];
        if (e == 0) { for (int i = 0; i <= r; i++) g_row_ptr[i] = 0; }
        else { int rp = rows[e - 1]; for (int i = rp + 1; i <= r; i++) g_row_ptr[i] = e; }
        if (e == E - 1) { for (int i = r + 1; i <= M; i++) g_row_ptr[i] = E; }
    }
}

// ---------------------------------------------------------------------------
// fp16 HMMA GEMM, LDSM-optimized tiling: Xtb(bf16) = A[M,128] @ W[128,128]
// Warp tile 32 rows x 64 cols (2 A-frags share each B-frag): per ks
//   2 A-LDSM.x4 + 4 B-LDSM.x4 -> 32 MMAs  (0.75 ldsm/MMA vs 1.125 before).
// 8 warps = 4 row-groups x 2 col-halves; TILE_M = 128.
// ---------------------------------------------------------------------------
__global__ __launch_bounds__(256, 2) void gemm_f16_kernel(const float* __restrict__ A,
                                                          int layer,
                                                          uint16_t* __restrict__ Xtb,
                                                          int M) {
    extern __shared__ char smem[];
    const uint32_t sb = smem_u32(smem);
    const int tid = threadIdx.x;
    const int wid = tid >> 5;
    const int lid = tid & 31;
    const int row0 = blockIdx.x * TILE_M;

    // ---- Stage W^T fp16 (swizzled): thread t -> n = t>>1, 128B half h = t&1
    {
        const uint4* gh = (const uint4*)g_wt[layer];
        int n = tid >> 1, h = tid & 1;
        uint32_t nsw = (uint32_t)((n & 7) << 4);
        uint32_t rbase = (uint32_t)(n * 256);
#pragma unroll
        for (int c = 0; c < 8; c++) {
            uint32_t kb = (uint32_t)(h * 128 + c * 16);
            *(uint4*)(smem + SM_WH + rbase + (kb ^ nsw)) = gh[n * 16 + h * 8 + c];
        }
    }

    // ---- Stage A rows -> fp16 (swizzled): thread t -> row t&127, half t>>7
    {
        int r = tid & 127, h = tid >> 7;
        int grow = row0 + r;
        if (grow >= M) grow = M - 1;
        const float4* src = (const float4*)(A + (size_t)grow * EMBED + h * 64);
        uint32_t rsw = (uint32_t)((r & 7) << 4);
        uint32_t rbase = (uint32_t)(r * 256);
#pragma unroll
        for (int c = 0; c < 8; c++) {            // 8 x 16B chunks (8 fp16 each)
            float4 f0 = src[c * 2];
            float4 f1 = src[c * 2 + 1];
            uint4 v = make_uint4(h2_bits(f0.x, f0.y), h2_bits(f0.z, f0.w),
                                 h2_bits(f1.x, f1.y), h2_bits(f1.z, f1.w));
            uint32_t kb = (uint32_t)(h * 128 + c * 16);
            *(uint4*)(smem + SM_XH + rbase + (kb ^ rsw)) = v;
        }
    }
    __syncthreads();

    // ---- Warp tile: rows rg*32..+31, cols ch*64..+63
    const int rg = wid >> 1;                // 0..3
    const int ch = wid & 1;                 // 0..1
    const uint32_t lsw = (uint32_t)((lid & 7) << 4);

    const int a_m = (((lid >> 3) & 1) << 3) + (lid & 7);
    const uint32_t a_kb0 = (uint32_t)((((lid >> 4) & 1) << 3) * 2);
    const uint32_t a_rbase0 = (uint32_t)((rg * 32 + a_m) * 256);        // rows +0..15
    const uint32_t a_rbase1 = (uint32_t)((rg * 32 + 16 + a_m) * 256);   // rows +16..31

    const int b_nl = (((lid >> 4) & 1) << 3) + (lid & 7);
    const uint32_t b_kb0 = (uint32_t)((((lid >> 3) & 1) << 3) * 2);
    const uint32_t b_rbase0 = (uint32_t)((ch * 64 + b_nl) * 256);

    float acc[2][8][4];
#pragma unroll
    for (int mb = 0; mb < 2; mb++)
#pragma unroll
        for (int nb = 0; nb < 8; nb++)
#pragma unroll
            for (int i = 0; i < 4; i++) acc[mb][nb][i] = 0.f;

#pragma unroll
    for (int ks = 0; ks < 8; ks++) {
        const uint32_t akb = (a_kb0 + (uint32_t)(ks * 32)) ^ lsw;
        const uint32_t bkb = (b_kb0 + (uint32_t)(ks * 32)) ^ lsw;
        uint32_t a00, a01, a02, a03, a10, a11, a12, a13;
        LDSM_X4(a00, a01, a02, a03, sb + SM_XH + a_rbase0 + akb);
        LDSM_X4(a10, a11, a12, a13, sb + SM_XH + a_rbase1 + akb);
#pragma unroll
        for (int p = 0; p < 4; p++) {
            const uint32_t brow = b_rbase0 + (uint32_t)(p * 16 * 256);
            uint32_t b0, b1, b2, b3;
            LDSM_X4(b0, b1, b2, b3, sb + SM_WH + brow + bkb);
            MMA_F16(acc[0][2 * p][0], acc[0][2 * p][1], acc[0][2 * p][2], acc[0][2 * p][3],
                    a00, a01, a02, a03, b0, b1);
            MMA_F16(acc[0][2 * p + 1][0], acc[0][2 * p + 1][1], acc[0][2 * p + 1][2], acc[0][2 * p + 1][3],
                    a00, a01, a02, a03, b2, b3);
            MMA_F16(acc[1][2 * p][0], acc[1][2 * p][1], acc[1][2 * p][2], acc[1][2 * p][3],
                    a10, a11, a12, a13, b0, b1);
            MMA_F16(acc[1][2 * p + 1][0], acc[1][2 * p + 1][1], acc[1][2 * p + 1][2], acc[1][2 * p + 1][3],
                    a10, a11, a12, a13, b2, b3);
        }
    }

    // ---- Epilogue: write bf16 xt. Frag: (c0,c1)=row g cols 2q..+1; (c2,c3)=row g+8
    const int g = lid >> 2;
    const int q = lid & 3;
#pragma unroll
    for (int mb = 0; mb < 2; mb++) {
        const int m0 = row0 + rg * 32 + mb * 16 + g;
        const int m1 = m0 + 8;
#pragma unroll
        for (int nb = 0; nb < 8; nb++) {
            int col = ch * 64 + nb * 8 + q * 2;
            if (m0 < M) *(uint32_t*)(Xtb + (size_t)m0 * EMBED + col) = bf2_bits(acc[mb][nb][0], acc[mb][nb][1]);
            if (m1 < M) *(uint32_t*)(Xtb + (size_t)m1 * EMBED + col) = bf2_bits(acc[mb][nb][2], acc[mb][nb][3]);
        }
    }
}

// ---------------------------------------------------------------------------
// SpMM + residual, bf16 gather, row-constant value — R13 structure verbatim
// (serial loop measured best; unrolled variants regress via L1tex contention).
//   out[r] = x[r] + v_r * sum_e bf16(xt)[cols[e]]
// ---------------------------------------------------------------------------
__global__ __launch_bounds__(256) void spmm_kernel(const float* __restrict__ x,
                                                   const int* __restrict__ cols,
                                                   const float* __restrict__ vals,
                                                   float* __restrict__ out,
                                                   float* __restrict__ out0,
                                                   int M) {
    int warp = (blockIdx.x * blockDim.x + threadIdx.x) >> 5;
    int lane = threadIdx.x & 31;
    if (warp >= M) return;
    int r = warp;
    int s = g_row_ptr[r];
    int e = g_row_ptr[r + 1];
    float vrow = (s < e) ? __ldg(vals + s) : 0.f;   // constant within the row

    float4 acc = make_float4(0.f, 0.f, 0.f, 0.f);
    for (int base = s; base < e; base += 32) {
        int idx = base + lane;
        int c = 0;
        if (idx < e) c = __ldg(cols + idx);
        int cnt = min(32, e - base);
        for (int j = 0; j < cnt; j++) {
            int cj = __shfl_sync(0xffffffffu, c, j);
            uint2 raw = ((const uint2*)(g_xtb + (size_t)cj * EMBED))[lane];
            acc.x += __uint_as_float(raw.x << 16);
            acc.y += __uint_as_float(raw.x & 0xffff0000u);
            acc.z += __uint_as_float(raw.y << 16);
            acc.w += __uint_as_float(raw.y & 0xffff0000u);
        }
    }
    float4 xv = ((const float4*)(x + (size_t)r * EMBED))[lane];
    if (out0) ((float4*)(out0 + (size_t)r * EMBED))[lane] = xv;
    float4 o;
    o.x = fmaf(vrow, acc.x, xv.x);
    o.y = fmaf(vrow, acc.y, xv.y);
    o.z = fmaf(vrow, acc.z, xv.z);
    o.w = fmaf(vrow, acc.w, xv.w);
    ((float4*)(out + (size_t)r * EMBED))[lane] = o;
}

// ---------------------------------------------------------------------------
// kernel_launch
// ---------------------------------------------------------------------------
extern "C" void kernel_launch(void* const* d_in, const int* in_sizes, int n_in,
                              void* d_out, int out_size) {
    const float* ue   = (const float*)d_in[0];
    const int*   rows = (const int*)  d_in[1];
    const int*   cols = (const int*)  d_in[2];
    const float* vals = (const float*)d_in[3];
    const float* W0   = (const float*)d_in[4];
    const float* W1   = (const float*)d_in[5];
    float* out = (float*)d_out;

    const int M = in_sizes[0] / EMBED;
    const int E = in_sizes[1];
    const size_t layer_elems = (size_t)M * EMBED;

    uint16_t* xtb_ptr;
    cudaGetSymbolAddress((void**)&xtb_ptr, g_xtb);

    cudaFuncSetAttribute(gemm_f16_kernel, cudaFuncAttributeMaxDynamicSharedMemorySize, SM_TOTAL);

    // Fused W-prep + CSR row_ptr build (one launch)
    prep_kernel<<<128 + (E + 255) / 256, 256>>>(W0, W1, rows, E, M);

    const int gemm_blocks = (M + TILE_M - 1) / TILE_M;
    const int spmm_blocks = (M * 32 + 255) / 256;

    // Layer 1 (SpMM also emits out[0] = user_embeds)
    gemm_f16_kernel<<<gemm_blocks, 256, SM_TOTAL>>>(ue, 0, xtb_ptr, M);
    spmm_kernel<<<spmm_blocks, 256>>>(ue, cols, vals, out + layer_elems, out, M);

    // Layer 2
    gemm_f16_kernel<<<gemm_blocks, 256, SM_TOTAL>>>(out + layer_elems, 1, xtb_ptr, M);
    spmm_kernel<<<spmm_blocks, 256>>>(out + layer_elems, cols, vals,
                                      out + 2 * layer_elems, nullptr, M);
}